// round 13
// baseline (speedup 1.0000x reference)
#include <cuda_runtime.h>
#include <cuda_fp16.h>
#include <cstdint>

#define NN      100000
#define DIM     256
#define NRELS   8
#define EPR     160000
#define NEDGES  (NRELS * EPR)
#define NBINS   (NRELS * NN)

#define KTOT    2304          // 8*256 aggregated + 256 self
#define TM      64            // output rows per block
#define KBE     64            // K halves per chunk = 128B
#define NCHUNK  (KTOT / KBE)  // 36

// smem: row stride 144B = 72 halves (64 data + 8 pad)
#define ROWB    144
#define B_STAGE (DIM * ROWB)          // 36864 (256 B-rows)
#define A_STAGE (TM * ROWB)           // 9216
#define OFF_B0  0
#define OFF_B1  B_STAGE
#define OFF_A0  (2 * B_STAGE)
#define OFF_A1  (2 * B_STAGE + A_STAGE)
#define SMEM_TOTAL (2 * B_STAGE + 2 * A_STAGE)   // 92160 -> 2 CTAs/SM

#define SCAN_BLK 1024
#define NSCANBLK ((NBINS + SCAN_BLK - 1) / SCAN_BLK)   // 782

// ---------------------------------------------------------------------------
// device scratch
// ---------------------------------------------------------------------------
__device__ int     g_src32[NEDGES];             // src sorted by (rel, dst)
__device__ int     g_idx_is_i32;
__device__ int     g_off[NBINS];                // scan -> (post-scatter) end offsets
__device__ int     g_off0[NBINS];               // start offsets
__device__ int     g_bsum[SCAN_BLK];
__device__ __half2 g_xh[NN * DIM / 2];          // x -> fp16
__device__ __half  g_Z[(size_t)NN * KTOT];      // [d][2304]: aggregates + x
__device__ __half  g_Wbig[DIM * KTOT];          // [n][2304]: {W_rel, W_self} stacked

// ---------------------------------------------------------------------------
// helpers
// ---------------------------------------------------------------------------
__device__ __forceinline__ void mma_f16(float c[4], const unsigned a[4], const unsigned b[2]) {
    asm volatile(
        "mma.sync.aligned.m16n8k16.row.col.f32.f16.f16.f32 "
        "{%0,%1,%2,%3}, {%4,%5,%6,%7}, {%8,%9}, {%0,%1,%2,%3};\n"
        : "+f"(c[0]), "+f"(c[1]), "+f"(c[2]), "+f"(c[3])
        : "r"(a[0]), "r"(a[1]), "r"(a[2]), "r"(a[3]), "r"(b[0]), "r"(b[1]));
}

__device__ __forceinline__ void cp_async16(uint32_t saddr, const void* g) {
    asm volatile("cp.async.cg.shared.global [%0], [%1], 16;" :: "r"(saddr), "l"(g) : "memory");
}
__device__ __forceinline__ void cp_commit() { asm volatile("cp.async.commit_group;" ::: "memory"); }
__device__ __forceinline__ void cp_wait1()  { asm volatile("cp.async.wait_group 1;" ::: "memory"); }

__device__ __forceinline__ int load_idx(const void* buf, long long i) {
    return g_idx_is_i32 ? ((const int*)buf)[i] : (int)((const long long*)buf)[i];
}

// ---------------------------------------------------------------------------
// prepass: dtype detect + counting sort of src by (rel, dst)
// ---------------------------------------------------------------------------
__global__ void detect_idx_kernel(const void* srcbuf) {
    const long long* p = (const long long*)srcbuf;
    int tid = threadIdx.x;
    int bad = 0;
    #pragma unroll
    for (int i = 0; i < 4; i++) {
        long long v = p[tid * 4 + i];
        if (v < 0 || v >= NN) bad = 1;
    }
    int any = __syncthreads_or(bad);
    if (tid == 0) g_idx_is_i32 = any;
}

__global__ void zero_hist_kernel() {
    int i = blockIdx.x * blockDim.x + threadIdx.x;
    if (i < NBINS) g_off[i] = 0;
}

__global__ void hist_kernel(const void* dstbuf) {
    long long i = (long long)blockIdx.x * blockDim.x + threadIdx.x;
    if (i >= NEDGES) return;
    int rel = (int)(i / EPR);
    int dst = load_idx(dstbuf, i);
    atomicAdd(&g_off[rel * NN + dst], 1);
}

__global__ void scan_local_kernel() {
    __shared__ int sh[SCAN_BLK];
    int i = blockIdx.x * SCAN_BLK + threadIdx.x;
    int v = (i < NBINS) ? g_off[i] : 0;
    sh[threadIdx.x] = v;
    __syncthreads();
    #pragma unroll
    for (int o = 1; o < SCAN_BLK; o <<= 1) {
        int t = (threadIdx.x >= o) ? sh[threadIdx.x - o] : 0;
        __syncthreads();
        sh[threadIdx.x] += t;
        __syncthreads();
    }
    if (i < NBINS) g_off[i] = sh[threadIdx.x] - v;   // exclusive
    if (threadIdx.x == SCAN_BLK - 1) g_bsum[blockIdx.x] = sh[threadIdx.x];
}

__global__ void scan_bsum_kernel() {
    __shared__ int sh[SCAN_BLK];
    int v = (threadIdx.x < NSCANBLK) ? g_bsum[threadIdx.x] : 0;
    sh[threadIdx.x] = v;
    __syncthreads();
    #pragma unroll
    for (int o = 1; o < SCAN_BLK; o <<= 1) {
        int t = (threadIdx.x >= o) ? sh[threadIdx.x - o] : 0;
        __syncthreads();
        sh[threadIdx.x] += t;
        __syncthreads();
    }
    if (threadIdx.x < NSCANBLK) g_bsum[threadIdx.x] = sh[threadIdx.x] - v;
}

__global__ void add_bsum_kernel() {
    int i = blockIdx.x * SCAN_BLK + threadIdx.x;
    if (i < NBINS) g_off[i] += g_bsum[blockIdx.x];
}

__global__ void copy_off_kernel() {
    int i = blockIdx.x * blockDim.x + threadIdx.x;
    if (i < NBINS) g_off0[i] = g_off[i];   // start offsets (pre-scatter)
}

__global__ void scatter_kernel(const void* srcbuf, const void* dstbuf) {
    long long i = (long long)blockIdx.x * blockDim.x + threadIdx.x;
    if (i >= NEDGES) return;
    int rel = (int)(i / EPR);
    int src = load_idx(srcbuf, i);
    int dst = load_idx(dstbuf, i);
    int pos = atomicAdd(&g_off[rel * NN + dst], 1);   // bumps to end offsets
    g_src32[pos] = src;
}

// ---------------------------------------------------------------------------
// conversions
// ---------------------------------------------------------------------------
__global__ void x_to_half(const float* __restrict__ x) {
    long long i = (long long)blockIdx.x * blockDim.x + threadIdx.x;
    if (i >= (long long)NN * DIM / 2) return;
    float2 v = ((const float2*)x)[i];
    g_xh[i] = __floats2half2_rn(v.x, v.y);
}

// Wbig[n][z*256 + k] = W_z[k][n];  z = 0..7 -> W_rel[z], z = 8 -> W_self
__global__ void build_wbig(const float* __restrict__ Wrel, const float* __restrict__ Wself) {
    __shared__ float t[32][33];
    int z = blockIdx.z;
    const float* S = (z < NRELS) ? (Wrel + (size_t)z * DIM * DIM) : Wself;
    int bn = blockIdx.x * 32, bk = blockIdx.y * 32;
    t[threadIdx.y][threadIdx.x] = S[(size_t)(bk + threadIdx.y) * DIM + bn + threadIdx.x];
    __syncthreads();
    int n = bn + threadIdx.y, k = bk + threadIdx.x;
    g_Wbig[(size_t)n * KTOT + z * DIM + k] = __float2half_rn(t[threadIdx.x][threadIdx.y]);
}

// copy x into Z[:, 2048:2304]
__global__ void xcopy_z() {
    long long i = (long long)blockIdx.x * blockDim.x + threadIdx.x;  // NN*128 half2
    if (i >= (long long)NN * 128) return;
    long long d = i >> 7, t = i & 127;
    ((__half2*)g_Z)[d * (KTOT / 2) + 1024 + t] = g_xh[d * 128 + t];
}

// ---------------------------------------------------------------------------
// Phase A: atomic-free aggregation. One warp per (rel, dst) bin:
// Z[d][r*256:(r+1)*256] = sum over edges of x[src] (fp32 accum, fp16 store).
// Empty bins store zeros (full Z init).
// ---------------------------------------------------------------------------
__global__ __launch_bounds__(256) void agg_kernel() {
    int wbin = blockIdx.x * 8 + (threadIdx.x >> 5);
    if (wbin >= NBINS) return;
    int lane = threadIdx.x & 31;
    int r = wbin / NN, d = wbin % NN;
    int e0 = g_off0[wbin], e1 = g_off[wbin];

    float acc[8] = {0.f, 0.f, 0.f, 0.f, 0.f, 0.f, 0.f, 0.f};
    for (int e = e0; e < e1; e++) {
        int src = g_src32[e];
        uint4 v = *reinterpret_cast<const uint4*>(
            (const char*)g_xh + (size_t)src * 512 + lane * 16);
        const __half2* h = reinterpret_cast<const __half2*>(&v);
        #pragma unroll
        for (int i = 0; i < 4; i++) {
            float2 f = __half22float2(h[i]);
            acc[2 * i]     += f.x;
            acc[2 * i + 1] += f.y;
        }
    }
    __half2 o[4];
    #pragma unroll
    for (int i = 0; i < 4; i++) o[i] = __floats2half2_rn(acc[2 * i], acc[2 * i + 1]);
    *reinterpret_cast<uint4*>(
        (char*)g_Z + ((size_t)d * KTOT + r * DIM + lane * 8) * 2) =
        *reinterpret_cast<const uint4*>(o);
}

// ---------------------------------------------------------------------------
// Phase B: dense fp16 GEMM  out[NN,256] = Zext[NN,2304] @ Wbig^T, fp32 accum,
// double-buffered cp.async, direct stores (no gather, no atomics).
// Block: 256 threads = 8 warps (2x4), tile M=64 x N=256, 36 K-chunks of 64.
// ---------------------------------------------------------------------------
__global__ __launch_bounds__(256, 2)
void dense_gemm_f16(const __half* __restrict__ Z,
                    const __half* __restrict__ WB,
                    float* __restrict__ out)
{
    extern __shared__ char smem[];
    const int tid = threadIdx.x;
    const long long base = (long long)blockIdx.x * TM;

    const int warp = tid >> 5;
    const int lane = tid & 31;
    const int wm = warp >> 2;
    const int wn = warp & 3;
    const int g  = lane >> 2;
    const int t4 = lane & 3;

    const int arow = tid >> 2;
    const int ac   = tid & 3;
    long long arglobal = base + arow;
    if (arglobal >= NN) arglobal = NN - 1;   // clamp (stores guarded)
    const char* aSrc = (const char*)Z + (size_t)arglobal * (KTOT * 2);
    const char* bSrc = (const char*)WB + (size_t)tid * (KTOT * 2);

    uint32_t sb;
    asm("{ .reg .u64 t; cvta.to.shared.u64 t, %1; cvt.u32.u64 %0, t; }" : "=r"(sb) : "l"(smem));
    const uint32_t offA[2] = { sb + OFF_A0, sb + OFF_A1 };
    const uint32_t offB[2] = { sb + OFF_B0, sb + OFF_B1 };

    auto stage = [&](int kc, int buf) {
        cp_async16(offA[buf] + arow * ROWB + ac * 16,       aSrc + kc * 128 + ac * 16);
        cp_async16(offA[buf] + arow * ROWB + (ac + 4) * 16, aSrc + kc * 128 + (ac + 4) * 16);
        #pragma unroll
        for (int i = 0; i < 8; i++)
            cp_async16(offB[buf] + tid * ROWB + i * 16, bSrc + kc * 128 + i * 16);
    };

    float c[2][8][4];
    #pragma unroll
    for (int mi = 0; mi < 2; mi++)
        #pragma unroll
        for (int j = 0; j < 8; j++)
            #pragma unroll
            for (int q = 0; q < 4; q++)
                c[mi][j][q] = 0.f;

    stage(0, 0);
    cp_commit();

    #pragma unroll 1
    for (int kc = 0; kc < NCHUNK; kc++) {
        if (kc + 1 < NCHUNK) stage(kc + 1, (kc + 1) & 1);
        cp_commit();
        cp_wait1();
        __syncthreads();

        const unsigned* Ab = (const unsigned*)(smem + ((kc & 1) ? OFF_A1 : OFF_A0));
        const unsigned* Bb = (const unsigned*)(smem + ((kc & 1) ? OFF_B1 : OFF_B0));

        #pragma unroll
        for (int s = 0; s < 4; s++) {
            unsigned a[2][4], b[8][2];
            #pragma unroll
            for (int mi = 0; mi < 2; mi++) {
                int rb = wm * 32 + mi * 16 + g;
                a[mi][0] = Ab[(size_t)rb       * 36 + s * 8 + t4];
                a[mi][1] = Ab[(size_t)(rb + 8) * 36 + s * 8 + t4];
                a[mi][2] = Ab[(size_t)rb       * 36 + s * 8 + t4 + 4];
                a[mi][3] = Ab[(size_t)(rb + 8) * 36 + s * 8 + t4 + 4];
            }
            #pragma unroll
            for (int j = 0; j < 8; j++) {
                int n = wn * 64 + j * 8 + g;
                b[j][0] = Bb[(size_t)n * 36 + s * 8 + t4];
                b[j][1] = Bb[(size_t)n * 36 + s * 8 + t4 + 4];
            }
            #pragma unroll
            for (int mi = 0; mi < 2; mi++)
                #pragma unroll
                for (int j = 0; j < 8; j++)
                    mma_f16(c[mi][j], a[mi], b[j]);
        }
        __syncthreads();
    }

    // direct store epilogue
    #pragma unroll
    for (int mi = 0; mi < 2; mi++) {
        #pragma unroll
        for (int half = 0; half < 2; half++) {
            int r = wm * 32 + mi * 16 + half * 8 + g;
            long long drow = base + r;
            if (drow >= NN) continue;
            float* orow = out + (size_t)drow * DIM + wn * 64;
            #pragma unroll
            for (int j = 0; j < 8; j++) {
                int col = j * 8 + t4 * 2;
                *reinterpret_cast<float2*>(orow + col) =
                    make_float2(c[mi][j][half * 2 + 0], c[mi][j][half * 2 + 1]);
            }
        }
    }
}

// ---------------------------------------------------------------------------
// LayerNorm over last dim (256). One warp per row.
// ---------------------------------------------------------------------------
__global__ void ln_kernel(float* __restrict__ out,
                          const float* __restrict__ gamma,
                          const float* __restrict__ beta)
{
    int row = blockIdx.x * 8 + (threadIdx.x >> 5);
    if (row >= NN) return;
    int lane = threadIdx.x & 31;
    float* p = out + (size_t)row * DIM;

    float4 v0 = *reinterpret_cast<const float4*>(p + lane * 4);
    float4 v1 = *reinterpret_cast<const float4*>(p + 128 + lane * 4);

    float s  = v0.x + v0.y + v0.z + v0.w + v1.x + v1.y + v1.z + v1.w;
    float sq = fmaf(v0.x, v0.x, fmaf(v0.y, v0.y, fmaf(v0.z, v0.z, v0.w * v0.w)))
             + fmaf(v1.x, v1.x, fmaf(v1.y, v1.y, fmaf(v1.z, v1.z, v1.w * v1.w)));

    #pragma unroll
    for (int o = 16; o; o >>= 1) {
        s  += __shfl_xor_sync(0xffffffffu, s,  o);
        sq += __shfl_xor_sync(0xffffffffu, sq, o);
    }

    float mean = s * (1.f / 256.f);
    float var  = sq * (1.f / 256.f) - mean * mean;
    float rs   = rsqrtf(var + 1e-5f);

    float4 g0 = *reinterpret_cast<const float4*>(gamma + lane * 4);
    float4 g1 = *reinterpret_cast<const float4*>(gamma + 128 + lane * 4);
    float4 b0 = *reinterpret_cast<const float4*>(beta + lane * 4);
    float4 b1 = *reinterpret_cast<const float4*>(beta + 128 + lane * 4);

    v0.x = (v0.x - mean) * rs * g0.x + b0.x;
    v0.y = (v0.y - mean) * rs * g0.y + b0.y;
    v0.z = (v0.z - mean) * rs * g0.z + b0.z;
    v0.w = (v0.w - mean) * rs * g0.w + b0.w;
    v1.x = (v1.x - mean) * rs * g1.x + b1.x;
    v1.y = (v1.y - mean) * rs * g1.y + b1.y;
    v1.z = (v1.z - mean) * rs * g1.z + b1.z;
    v1.w = (v1.w - mean) * rs * g1.w + b1.w;

    *reinterpret_cast<float4*>(p + lane * 4)       = v0;
    *reinterpret_cast<float4*>(p + 128 + lane * 4) = v1;
}

extern "C" void kernel_launch(void* const* d_in, const int* in_sizes, int n_in,
                              void* d_out, int out_size)
{
    const float* x     = (const float*)d_in[0];
    const void*  srcb  = d_in[1];
    const void*  dstb  = d_in[2];
    const float* Wself = (const float*)d_in[3];
    const float* Wrel  = (const float*)d_in[4];
    const float* gamma = (const float*)d_in[5];
    const float* beta  = (const float*)d_in[6];
    float* out = (float*)d_out;

    void *pZ = nullptr, *pWB = nullptr;
    cudaGetSymbolAddress(&pZ, g_Z);
    cudaGetSymbolAddress(&pWB, g_Wbig);

    cudaFuncSetAttribute(dense_gemm_f16,
                         cudaFuncAttributeMaxDynamicSharedMemorySize, SMEM_TOTAL);

    // --- prepass: dtype detect + counting sort of src by (rel, dst) ---
    detect_idx_kernel<<<1, 256>>>(srcb);
    zero_hist_kernel<<<(NBINS + 1023) / 1024, 1024>>>();
    hist_kernel<<<(NEDGES + 255) / 256, 256>>>(dstb);
    scan_local_kernel<<<NSCANBLK, SCAN_BLK>>>();
    scan_bsum_kernel<<<1, SCAN_BLK>>>();
    add_bsum_kernel<<<NSCANBLK, SCAN_BLK>>>();
    copy_off_kernel<<<(NBINS + 1023) / 1024, 1024>>>();
    scatter_kernel<<<(NEDGES + 255) / 256, 256>>>(srcb, dstb);

    // --- conversions ---
    {
        long long nh2 = (long long)NN * DIM / 2;
        x_to_half<<<(int)((nh2 + 255) / 256), 256>>>(x);
        build_wbig<<<dim3(8, 8, NRELS + 1), dim3(32, 32)>>>(Wrel, Wself);
    }

    // --- Phase A: atomic-free neighbor aggregation into Z ---
    agg_kernel<<<(NBINS + 7) / 8, 256>>>();
    {
        long long n = (long long)NN * 128;
        xcopy_z<<<(int)((n + 255) / 256), 256>>>();
    }

    // --- Phase B: one dense GEMM produces out (self + all relations) ---
    dense_gemm_f16<<<(NN + TM - 1) / TM, 256, SMEM_TOTAL>>>(
        (const __half*)pZ, (const __half*)pWB, out);

    // --- LayerNorm ---
    ln_kernel<<<(NN + 7) / 8, 256>>>(out, gamma, beta);
}

// round 14
// speedup vs baseline: 1.3520x; 1.3520x over previous
#include <cuda_runtime.h>
#include <cuda_fp16.h>
#include <cstdint>

#define NN      100000
#define DIM     256
#define NRELS   8
#define EPR     160000
#define NEDGES  (NRELS * EPR)
#define NBINS   (NRELS * NN)

#define KTOT    2304              // 8 relations * 256 + self 256
#define TM      64                // dst rows per block
#define NZ      9                 // 8 relations + self
#define NCHTOT  36                // 9 * 4 K-chunks of 64 halves

// ---- smem layout ----
// A aggregate buffers: 64 rows x 132 words (256 halves + 8 pad halves)
#define AG_STRIDE 132                       // words per row
#define AG_BYTES  (TM * AG_STRIDE * 4)      // 33792
#define OFF_AG0   0
#define OFF_AG1   AG_BYTES
// B staging: 256 n-rows x 36 words (64 halves + 8 pad)
#define B_STRIDE  36
#define B_BYTES   (DIM * B_STRIDE * 4)      // 36864
#define OFF_B0    (2 * AG_BYTES)            // 67584
#define OFF_B1    (OFF_B0 + B_BYTES)        // 104448
#define SMEM_TOTAL (OFF_B1 + B_BYTES)       // 141312 -> 1 CTA/SM

#define SCAN_BLK 1024
#define NSCANBLK ((NBINS + SCAN_BLK - 1) / SCAN_BLK)   // 782

// ---------------------------------------------------------------------------
// device scratch
// ---------------------------------------------------------------------------
__device__ int     g_src32[NEDGES];             // src sorted by (rel, dst)
__device__ int     g_idx_is_i32;
__device__ int     g_off[NBINS];                // end offsets (post-scatter)
__device__ int     g_off0[NBINS];               // start offsets
__device__ int     g_bsum[SCAN_BLK];
__device__ __half2 g_xh[NN * DIM / 2];          // x -> fp16 (51.2MB, L2-resident)
__device__ __half  g_Wbig[DIM * KTOT];          // [n][2304]: {W_rel 0..7, W_self}

// ---------------------------------------------------------------------------
// helpers
// ---------------------------------------------------------------------------
__device__ __forceinline__ void mma_f16(float c[4], const unsigned a[4], const unsigned b[2]) {
    asm volatile(
        "mma.sync.aligned.m16n8k16.row.col.f32.f16.f16.f32 "
        "{%0,%1,%2,%3}, {%4,%5,%6,%7}, {%8,%9}, {%0,%1,%2,%3};\n"
        : "+f"(c[0]), "+f"(c[1]), "+f"(c[2]), "+f"(c[3])
        : "r"(a[0]), "r"(a[1]), "r"(a[2]), "r"(a[3]), "r"(b[0]), "r"(b[1]));
}

__device__ __forceinline__ void cp_async16(uint32_t saddr, const void* g) {
    asm volatile("cp.async.cg.shared.global [%0], [%1], 16;" :: "r"(saddr), "l"(g) : "memory");
}
__device__ __forceinline__ void cp_commit() { asm volatile("cp.async.commit_group;" ::: "memory"); }
__device__ __forceinline__ void cp_wait1()  { asm volatile("cp.async.wait_group 1;" ::: "memory"); }
__device__ __forceinline__ void barn(int id, int cnt) {
    asm volatile("bar.sync %0, %1;" :: "r"(id), "r"(cnt) : "memory");
}

__device__ __forceinline__ int load_idx(const void* buf, long long i) {
    return g_idx_is_i32 ? ((const int*)buf)[i] : (int)((const long long*)buf)[i];
}

// ---------------------------------------------------------------------------
// prepass: dtype detect + counting sort of src by (rel, dst)
// ---------------------------------------------------------------------------
__global__ void detect_idx_kernel(const void* srcbuf) {
    const long long* p = (const long long*)srcbuf;
    int tid = threadIdx.x;
    int bad = 0;
    #pragma unroll
    for (int i = 0; i < 4; i++) {
        long long v = p[tid * 4 + i];
        if (v < 0 || v >= NN) bad = 1;
    }
    int any = __syncthreads_or(bad);
    if (tid == 0) g_idx_is_i32 = any;
}

__global__ void zero_hist_kernel() {
    int i = blockIdx.x * blockDim.x + threadIdx.x;
    if (i < NBINS) g_off[i] = 0;
}

__global__ void hist_kernel(const void* dstbuf) {
    long long i = (long long)blockIdx.x * blockDim.x + threadIdx.x;
    if (i >= NEDGES) return;
    int rel = (int)(i / EPR);
    int dst = load_idx(dstbuf, i);
    atomicAdd(&g_off[rel * NN + dst], 1);
}

__global__ void scan_local_kernel() {
    __shared__ int sh[SCAN_BLK];
    int i = blockIdx.x * SCAN_BLK + threadIdx.x;
    int v = (i < NBINS) ? g_off[i] : 0;
    sh[threadIdx.x] = v;
    __syncthreads();
    #pragma unroll
    for (int o = 1; o < SCAN_BLK; o <<= 1) {
        int t = (threadIdx.x >= o) ? sh[threadIdx.x - o] : 0;
        __syncthreads();
        sh[threadIdx.x] += t;
        __syncthreads();
    }
    if (i < NBINS) g_off[i] = sh[threadIdx.x] - v;   // exclusive
    if (threadIdx.x == SCAN_BLK - 1) g_bsum[blockIdx.x] = sh[threadIdx.x];
}

__global__ void scan_bsum_kernel() {
    __shared__ int sh[SCAN_BLK];
    int v = (threadIdx.x < NSCANBLK) ? g_bsum[threadIdx.x] : 0;
    sh[threadIdx.x] = v;
    __syncthreads();
    #pragma unroll
    for (int o = 1; o < SCAN_BLK; o <<= 1) {
        int t = (threadIdx.x >= o) ? sh[threadIdx.x - o] : 0;
        __syncthreads();
        sh[threadIdx.x] += t;
        __syncthreads();
    }
    if (threadIdx.x < NSCANBLK) g_bsum[threadIdx.x] = sh[threadIdx.x] - v;
}

__global__ void add_bsum_kernel() {
    int i = blockIdx.x * SCAN_BLK + threadIdx.x;
    if (i < NBINS) g_off[i] += g_bsum[blockIdx.x];
}

__global__ void copy_off_kernel() {
    int i = blockIdx.x * blockDim.x + threadIdx.x;
    if (i < NBINS) g_off0[i] = g_off[i];   // start offsets (pre-scatter)
}

__global__ void scatter_kernel(const void* srcbuf, const void* dstbuf) {
    long long i = (long long)blockIdx.x * blockDim.x + threadIdx.x;
    if (i >= NEDGES) return;
    int rel = (int)(i / EPR);
    int src = load_idx(srcbuf, i);
    int dst = load_idx(dstbuf, i);
    int pos = atomicAdd(&g_off[rel * NN + dst], 1);   // bumps to end offsets
    g_src32[pos] = src;
}

// ---------------------------------------------------------------------------
// conversions
// ---------------------------------------------------------------------------
__global__ void x_to_half(const float* __restrict__ x) {
    long long i = (long long)blockIdx.x * blockDim.x + threadIdx.x;
    if (i >= (long long)NN * DIM / 2) return;
    float2 v = ((const float2*)x)[i];
    g_xh[i] = __floats2half2_rn(v.x, v.y);
}

// Wbig[n][z*256 + k] = W_z[k][n];  z = 0..7 -> W_rel[z], z = 8 -> W_self
__global__ void build_wbig(const float* __restrict__ Wrel, const float* __restrict__ Wself) {
    __shared__ float t[32][33];
    int z = blockIdx.z;
    const float* S = (z < NRELS) ? (Wrel + (size_t)z * DIM * DIM) : Wself;
    int bn = blockIdx.x * 32, bk = blockIdx.y * 32;
    t[threadIdx.y][threadIdx.x] = S[(size_t)(bk + threadIdx.y) * DIM + bn + threadIdx.x];
    __syncthreads();
    int n = bn + threadIdx.y, k = bk + threadIdx.x;
    g_Wbig[(size_t)n * KTOT + z * DIM + k] = __float2half_rn(t[threadIdx.x][threadIdx.y]);
}

// ---------------------------------------------------------------------------
// Fused RGCN kernel: per block, 64 consecutive dst rows.
// Warps 0-7 (tid<256): B-pipelined fp16 MMA over 9 relation-slices (z=0..7
// relations, z=8 self), consuming the double-buffered aggregate A_z.
// Warps 8-15: aggregate relation z+1 (CSR neighbor sums, fp32 acc -> fp16 smem)
// while MMA runs relation z. One __syncthreads per relation hands off.
// Direct float2 stores. No atomics anywhere.
// ---------------------------------------------------------------------------
__global__ __launch_bounds__(512, 1)
void fused_rgcn(const __half* __restrict__ XH,
                const __half* __restrict__ WB,
                float* __restrict__ out)
{
    extern __shared__ char smem[];
    const int tid = threadIdx.x;
    const long long base = (long long)blockIdx.x * TM;

    uint32_t sb;
    asm("{ .reg .u64 t; cvta.to.shared.u64 t, %1; cvt.u32.u64 %0, t; }" : "=r"(sb) : "l"(smem));

    const int lane = tid & 31;

    // ---- aggregation (agg warps): fill A buffer (zz&1) with relation zz ----
    auto aggregate = [&](int zz) {
        const int awarp = (tid >> 5) - 8;             // 0..7
        char* Ag = smem + ((zz & 1) ? OFF_AG1 : OFF_AG0);
        #pragma unroll 1
        for (int rr = 0; rr < 8; rr++) {
            int r = awarp * 8 + rr;
            long long d = base + r;
            float acc[8] = {0.f, 0.f, 0.f, 0.f, 0.f, 0.f, 0.f, 0.f};
            if (d < NN) {
                if (zz < 8) {
                    int bin = zz * NN + (int)d;
                    int e0 = g_off0[bin], e1 = g_off[bin];
                    for (int e = e0; e < e1; e++) {
                        int src = g_src32[e];
                        uint4 v = *reinterpret_cast<const uint4*>(
                            (const char*)XH + (size_t)src * 512 + lane * 16);
                        const __half2* h = reinterpret_cast<const __half2*>(&v);
                        #pragma unroll
                        for (int i = 0; i < 4; i++) {
                            float2 f = __half22float2(h[i]);
                            acc[2 * i]     += f.x;
                            acc[2 * i + 1] += f.y;
                        }
                    }
                } else {   // self: copy x[d]
                    uint4 v = *reinterpret_cast<const uint4*>(
                        (const char*)XH + (size_t)d * 512 + lane * 16);
                    const __half2* h = reinterpret_cast<const __half2*>(&v);
                    #pragma unroll
                    for (int i = 0; i < 4; i++) {
                        float2 f = __half22float2(h[i]);
                        acc[2 * i]     += f.x;
                        acc[2 * i + 1] += f.y;
                    }
                }
            }
            __half2 o[4];
            #pragma unroll
            for (int i = 0; i < 4; i++) o[i] = __floats2half2_rn(acc[2 * i], acc[2 * i + 1]);
            *reinterpret_cast<uint4*>(Ag + (size_t)(r * AG_STRIDE + lane * 4) * 4) =
                *reinterpret_cast<const uint4*>(o);
        }
    };

    // ---- MMA-side identifiers ----
    const int warp = tid >> 5;        // 0..7 for MMA warps
    const int wm = warp >> 2;         // 0..1
    const int wn = warp & 3;          // 0..3
    const int g  = lane >> 2;         // 0..7
    const int t4 = lane & 3;          // 0..3

    const char* bSrc = (const char*)WB + (size_t)tid * (KTOT * 2);   // n-row = tid (tid<256)
    const uint32_t offB[2] = { sb + OFF_B0, sb + OFF_B1 };

    auto stageB = [&](int kc, int buf) {   // kc = global chunk 0..35
        #pragma unroll
        for (int i = 0; i < 8; i++)
            cp_async16(offB[buf] + tid * (B_STRIDE * 4) + i * 16, bSrc + kc * 128 + i * 16);
    };

    float c[2][8][4];
    #pragma unroll
    for (int mi = 0; mi < 2; mi++)
        #pragma unroll
        for (int j = 0; j < 8; j++)
            #pragma unroll
            for (int q = 0; q < 4; q++)
                c[mi][j][q] = 0.f;

    // ---- prologue ----
    if (tid < 256) {
        stageB(0, 0);
        cp_commit();
    } else {
        aggregate(0);                  // A_0 into buffer 0
    }
    __syncthreads();

    // ---- main loop over relation slices ----
    #pragma unroll 1
    for (int z = 0; z < NZ; z++) {
        if (tid < 256) {
            const unsigned* Ab = (const unsigned*)(smem + ((z & 1) ? OFF_AG1 : OFF_AG0));
            #pragma unroll 1
            for (int kc4 = 0; kc4 < 4; kc4++) {
                const int kc = z * 4 + kc4;
                if (kc + 1 < NCHTOT) stageB(kc + 1, (kc + 1) & 1);
                cp_commit();           // uniform group accounting
                cp_wait1();            // chunk kc's group complete
                barn(1, 256);          // visible to all MMA warps

                const unsigned* Bb = (const unsigned*)(smem + ((kc & 1) ? OFF_B1 : OFF_B0));
                const int abase = kc4 * 32;

                #pragma unroll
                for (int s = 0; s < 4; s++) {
                    unsigned a[2][4], b[8][2];
                    #pragma unroll
                    for (int mi = 0; mi < 2; mi++) {
                        int rb = wm * 32 + mi * 16 + g;
                        a[mi][0] = Ab[(size_t)rb       * AG_STRIDE + abase + s * 8 + t4];
                        a[mi][1] = Ab[(size_t)(rb + 8) * AG_STRIDE + abase + s * 8 + t4];
                        a[mi][2] = Ab[(size_t)rb       * AG_STRIDE + abase + s * 8 + t4 + 4];
                        a[mi][3] = Ab[(size_t)(rb + 8) * AG_STRIDE + abase + s * 8 + t4 + 4];
                    }
                    #pragma unroll
                    for (int j = 0; j < 8; j++) {
                        int n = wn * 64 + j * 8 + g;
                        b[j][0] = Bb[(size_t)n * B_STRIDE + s * 8 + t4];
                        b[j][1] = Bb[(size_t)n * B_STRIDE + s * 8 + t4 + 4];
                    }
                    #pragma unroll
                    for (int mi = 0; mi < 2; mi++)
                        #pragma unroll
                        for (int j = 0; j < 8; j++)
                            mma_f16(c[mi][j], a[mi], b[j]);
                }
                barn(1, 256);          // all MMA warps done reading B buf (WAR)
            }
        } else {
            if (z + 1 < NZ) aggregate(z + 1);   // next relation (or self) into other A buf
        }
        __syncthreads();               // A handoff for z+1
    }

    // ---- epilogue: direct stores (MMA warps) ----
    if (tid < 256) {
        #pragma unroll
        for (int mi = 0; mi < 2; mi++) {
            #pragma unroll
            for (int half = 0; half < 2; half++) {
                int r = wm * 32 + mi * 16 + half * 8 + g;
                long long drow = base + r;
                if (drow >= NN) continue;
                float* orow = out + (size_t)drow * DIM + wn * 64;
                #pragma unroll
                for (int j = 0; j < 8; j++) {
                    int col = j * 8 + t4 * 2;
                    *reinterpret_cast<float2*>(orow + col) =
                        make_float2(c[mi][j][half * 2 + 0], c[mi][j][half * 2 + 1]);
                }
            }
        }
    }
}

// ---------------------------------------------------------------------------
// LayerNorm over last dim (256). One warp per row.
// ---------------------------------------------------------------------------
__global__ void ln_kernel(float* __restrict__ out,
                          const float* __restrict__ gamma,
                          const float* __restrict__ beta)
{
    int row = blockIdx.x * 8 + (threadIdx.x >> 5);
    if (row >= NN) return;
    int lane = threadIdx.x & 31;
    float* p = out + (size_t)row * DIM;

    float4 v0 = *reinterpret_cast<const float4*>(p + lane * 4);
    float4 v1 = *reinterpret_cast<const float4*>(p + 128 + lane * 4);

    float s  = v0.x + v0.y + v0.z + v0.w + v1.x + v1.y + v1.z + v1.w;
    float sq = fmaf(v0.x, v0.x, fmaf(v0.y, v0.y, fmaf(v0.z, v0.z, v0.w * v0.w)))
             + fmaf(v1.x, v1.x, fmaf(v1.y, v1.y, fmaf(v1.z, v1.z, v1.w * v1.w)));

    #pragma unroll
    for (int o = 16; o; o >>= 1) {
        s  += __shfl_xor_sync(0xffffffffu, s,  o);
        sq += __shfl_xor_sync(0xffffffffu, sq, o);
    }

    float mean = s * (1.f / 256.f);
    float var  = sq * (1.f / 256.f) - mean * mean;
    float rs   = rsqrtf(var + 1e-5f);

    float4 g0 = *reinterpret_cast<const float4*>(gamma + lane * 4);
    float4 g1 = *reinterpret_cast<const float4*>(gamma + 128 + lane * 4);
    float4 b0 = *reinterpret_cast<const float4*>(beta + lane * 4);
    float4 b1 = *reinterpret_cast<const float4*>(beta + 128 + lane * 4);

    v0.x = (v0.x - mean) * rs * g0.x + b0.x;
    v0.y = (v0.y - mean) * rs * g0.y + b0.y;
    v0.z = (v0.z - mean) * rs * g0.z + b0.z;
    v0.w = (v0.w - mean) * rs * g0.w + b0.w;
    v1.x = (v1.x - mean) * rs * g1.x + b1.x;
    v1.y = (v1.y - mean) * rs * g1.y + b1.y;
    v1.z = (v1.z - mean) * rs * g1.z + b1.z;
    v1.w = (v1.w - mean) * rs * g1.w + b1.w;

    *reinterpret_cast<float4*>(p + lane * 4)       = v0;
    *reinterpret_cast<float4*>(p + 128 + lane * 4) = v1;
}

extern "C" void kernel_launch(void* const* d_in, const int* in_sizes, int n_in,
                              void* d_out, int out_size)
{
    const float* x     = (const float*)d_in[0];
    const void*  srcb  = d_in[1];
    const void*  dstb  = d_in[2];
    const float* Wself = (const float*)d_in[3];
    const float* Wrel  = (const float*)d_in[4];
    const float* gamma = (const float*)d_in[5];
    const float* beta  = (const float*)d_in[6];
    float* out = (float*)d_out;

    void *pXh = nullptr, *pWB = nullptr;
    cudaGetSymbolAddress(&pXh, g_xh);
    cudaGetSymbolAddress(&pWB, g_Wbig);

    cudaFuncSetAttribute(fused_rgcn,
                         cudaFuncAttributeMaxDynamicSharedMemorySize, SMEM_TOTAL);

    // --- prepass: dtype detect + counting sort of src by (rel, dst) ---
    detect_idx_kernel<<<1, 256>>>(srcb);
    zero_hist_kernel<<<(NBINS + 1023) / 1024, 1024>>>();
    hist_kernel<<<(NEDGES + 255) / 256, 256>>>(dstb);
    scan_local_kernel<<<NSCANBLK, SCAN_BLK>>>();
    scan_bsum_kernel<<<1, SCAN_BLK>>>();
    add_bsum_kernel<<<NSCANBLK, SCAN_BLK>>>();
    copy_off_kernel<<<(NBINS + 1023) / 1024, 1024>>>();
    scatter_kernel<<<(NEDGES + 255) / 256, 256>>>(srcb, dstb);

    // --- conversions ---
    {
        long long nh2 = (long long)NN * DIM / 2;
        x_to_half<<<(int)((nh2 + 255) / 256), 256>>>(x);
        build_wbig<<<dim3(8, 8, NRELS + 1), dim3(32, 32)>>>(Wrel, Wself);
    }

    // --- fused aggregate + GEMM: out = [agg_r | x] @ {W_r | W_self} ---
    fused_rgcn<<<(NN + TM - 1) / TM, 512, SMEM_TOTAL>>>(
        (const __half*)pXh, (const __half*)pWB, out);

    // --- LayerNorm ---
    ln_kernel<<<(NN + 7) / 8, 256>>>(out, gamma, beta);
}